// round 6
// baseline (speedup 1.0000x reference)
#include <cuda_runtime.h>
#include <math.h>
#include <stdint.h>

#define NPIX  16384   // 4*64*64
#define CDIM  128

// Scratch (device globals: no allocations allowed)
__device__ float g_q[NPIX * CDIM];
__device__ float g_k[NPIX * CDIM];
__device__ float g_v[NPIX * CDIM];
__device__ float g_att[NPIX * CDIM];

// ---------------- tf32 helpers ----------------
__device__ __forceinline__ uint32_t f2tf32(float f) {
    uint32_t r;
    asm("cvt.rna.tf32.f32 %0, %1;" : "=r"(r) : "f"(f));
    return r;
}
__device__ __forceinline__ void mma_tf32(float* d, const uint32_t* a,
                                         uint32_t b0, uint32_t b1) {
    asm volatile(
        "mma.sync.aligned.m16n8k8.row.col.f32.tf32.tf32.f32 "
        "{%0,%1,%2,%3}, {%4,%5,%6,%7}, {%8,%9}, {%0,%1,%2,%3};"
        : "+f"(d[0]), "+f"(d[1]), "+f"(d[2]), "+f"(d[3])
        : "r"(a[0]), "r"(a[1]), "r"(a[2]), "r"(a[3]), "r"(b0), "r"(b1));
}

// ---------------------------------------------------------------------------
// TF32 tensor-core GEMM v3: BM=64, FULL K=128 resident in smem, single
// __syncthreads, then 16 fully-unrolled k-steps of straight-line LDS+HMMA.
// 8 warps: 2 over M (32 rows), 4 over N (32 cols). Warp tile 32x32.
// ---------------------------------------------------------------------------
#define PA 132   // As row stride (u32): fragment banks = 4g+t -> conflict-free
#define PB 132   // Bs row stride
#define GEMM_SMEM ((64 * PA + 128 * PB) * 4)   // 101376 B

template<int LDW, bool IS_QKV>
__global__ __launch_bounds__(256) void gemm_tf32(
    const float* __restrict__ A,      // [16384, 128] (ignored for proj)
    const float* __restrict__ W,      // [128, LDW]
    const float* __restrict__ bias,   // [LDW]
    float* __restrict__ outp)         // proj output
{
    extern __shared__ uint32_t smem_g[];
    uint32_t* As = smem_g;                    // [64][PA]  (m-major, k minor)
    uint32_t* Bs = smem_g + 64 * PA;          // [128][PB] (k-major, n minor)

    const int bm   = blockIdx.x;
    const int bn   = blockIdx.y;
    const int tid  = threadIdx.x;
    const int lane = tid & 31;
    const int wrp  = tid >> 5;
    const int g    = lane >> 2;
    const int t    = lane & 3;
    const int wm   = wrp & 1;        // 2 warps along M (32 rows each)
    const int wn   = wrp >> 1;       // 4 warps along N (32 cols each)

    const float* Aptr = IS_QKV ? A : g_att;

    // ---- Stage A: 64 rows x 128 k (8 float4 per thread), cvt to tf32
    #pragma unroll
    for (int i = 0; i < 8; i++) {
        int f4  = tid + i * 256;             // 0..2047
        int r   = f4 >> 5;                   // row 0..63
        int c4  = f4 & 31;                   // k-group 0..31
        float4 v = *(const float4*)&Aptr[(size_t)(bm * 64 + r) * 128 + c4 * 4];
        As[r * PA + c4 * 4 + 0] = f2tf32(v.x);
        As[r * PA + c4 * 4 + 1] = f2tf32(v.y);
        As[r * PA + c4 * 4 + 2] = f2tf32(v.z);
        As[r * PA + c4 * 4 + 3] = f2tf32(v.w);
    }
    // ---- Stage B: 128 k x 128 n (16 float4 per thread)
    #pragma unroll
    for (int i = 0; i < 16; i++) {
        int f4  = tid + i * 256;
        int rb  = f4 >> 5;                   // k 0..127
        int cb4 = f4 & 31;                   // n-group
        float4 v = *(const float4*)&W[(size_t)rb * LDW + bn * 128 + cb4 * 4];
        Bs[rb * PB + cb4 * 4 + 0] = f2tf32(v.x);
        Bs[rb * PB + cb4 * 4 + 1] = f2tf32(v.y);
        Bs[rb * PB + cb4 * 4 + 2] = f2tf32(v.z);
        Bs[rb * PB + cb4 * 4 + 3] = f2tf32(v.w);
    }
    __syncthreads();

    float acc[2][4][4];
    #pragma unroll
    for (int i = 0; i < 2; i++)
        #pragma unroll
        for (int j = 0; j < 4; j++)
            #pragma unroll
            for (int c = 0; c < 4; c++) acc[i][j][c] = 0.f;

    // ---- Main loop: 16 k-steps, fully unrolled, no syncs, no branches
    #pragma unroll
    for (int ks = 0; ks < 16; ks++) {
        const int k0 = ks * 8;
        uint32_t a[2][4];
        #pragma unroll
        for (int mi = 0; mi < 2; mi++) {
            int rb = wm * 32 + mi * 16;
            a[mi][0] = As[(rb + g)     * PA + k0 + t];
            a[mi][1] = As[(rb + g + 8) * PA + k0 + t];
            a[mi][2] = As[(rb + g)     * PA + k0 + t + 4];
            a[mi][3] = As[(rb + g + 8) * PA + k0 + t + 4];
        }
        #pragma unroll
        for (int ni = 0; ni < 4; ni++) {
            int cb = wn * 32 + ni * 8;
            uint32_t b0 = Bs[(k0 + t)     * PB + cb + g];
            uint32_t b1 = Bs[(k0 + t + 4) * PB + cb + g];
            mma_tf32(acc[0][ni], a[0], b0, b1);
            mma_tf32(acc[1][ni], a[1], b0, b1);
        }
    }

    // ---- Epilogue
    const float scale = (IS_QKV && bn == 0) ? 0.17677669529663688f : 1.0f;
    float* dst;
    if (IS_QKV) dst = (bn == 0) ? g_q : (bn == 1) ? g_k : g_v;
    else        dst = outp;

    #pragma unroll
    for (int ni = 0; ni < 4; ni++) {
        int c  = wn * 32 + ni * 8 + t * 2;
        float b0 = bias[(IS_QKV ? bn * 128 : 0) + c];
        float b1 = bias[(IS_QKV ? bn * 128 : 0) + c + 1];
        #pragma unroll
        for (int mi = 0; mi < 2; mi++) {
            int r0 = bm * 64 + wm * 32 + mi * 16 + g;
            float2 v0 = make_float2((acc[mi][ni][0] + b0) * scale,
                                    (acc[mi][ni][1] + b1) * scale);
            float2 v1 = make_float2((acc[mi][ni][2] + b0) * scale,
                                    (acc[mi][ni][3] + b1) * scale);
            *(float2*)&dst[(size_t)r0 * 128 + c]       = v0;
            *(float2*)&dst[(size_t)(r0 + 8) * 128 + c] = v1;
        }
    }
}

// ---------------------------------------------------------------------------
// Neighborhood attention (R4 version): 8x8 pixel tile, ONE 14x14 halo buffer
// reused (K for score pass, then restaged with V) -> 103.5KB smem, 2 CTAs/SM.
// ---------------------------------------------------------------------------
#define SM_STRIDE 132                       // floats per (ny,nx) entry
#define SM_FLOATS (14 * 14 * SM_STRIDE)     // 25872 floats = 103488 B

__global__ __launch_bounds__(256, 2) void natten_kernel(const float* __restrict__ rpb)
{
    extern __shared__ float sm[];
    float* KVs = sm;

    const int tid  = threadIdx.x;
    const int tile = blockIdx.x & 63;
    const int b    = blockIdx.x >> 6;
    const int Y    = (tile >> 3) * 8;
    const int X    = (tile & 7) * 8;

    const int hb = min(max(Y - 3, 0), 50);
    const int wb = min(max(X - 3, 0), 50);

    // Stage K halo
    {
        const float4* gk4 = (const float4*)g_k;
        float4* s4 = (float4*)KVs;
        for (int i = tid; i < 14 * 14 * 32; i += 256) {
            int ny  = i / 448;
            int rem = i - ny * 448;
            int nx  = rem >> 5;
            int c4  = rem & 31;
            s4[(ny * 14 + nx) * 33 + c4] =
                gk4[(((b * 64 + hb + ny) * 64) + wb + nx) * 32 + c4];
        }
    }

    const int px   = tid & 63;
    const int head = tid >> 6;
    const int py   = px >> 3;
    const int pxx  = px & 7;
    const int y    = Y + py;
    const int x    = X + pxx;
    const int pixel = (b * 64 + y) * 64 + x;

    const int sh = min(max(y - 3, 0), 57);
    const int sw = min(max(x - 3, 0), 57);
    const int ry = sh - hb;
    const int rx = sw - wb;
    const int bias_base = head * 169 + (sh - y + 6) * 13 + (sw - x + 6);

    float4 q[8];
    {
        const float4* gq4 = (const float4*)g_q;
        int base = pixel * 32 + head * 8;
        #pragma unroll
        for (int i = 0; i < 8; i++) q[i] = gq4[base + i];
    }
    __syncthreads();

    // Pass 1: scores
    float s[49];
    #pragma unroll
    for (int iy = 0; iy < 7; iy++) {
        #pragma unroll
        for (int ix = 0; ix < 7; ix++) {
            const float* kp = &KVs[((ry + iy) * 14 + (rx + ix)) * SM_STRIDE + head * 32];
            float d0 = 0.f, d1 = 0.f, d2 = 0.f, d3 = 0.f;
            #pragma unroll
            for (int i = 0; i < 2; i++) {
                float4 k0 = *(const float4*)&kp[i * 16 + 0];
                float4 k1 = *(const float4*)&kp[i * 16 + 4];
                float4 k2 = *(const float4*)&kp[i * 16 + 8];
                float4 k3 = *(const float4*)&kp[i * 16 + 12];
                float4 q0 = q[i * 4 + 0], q1 = q[i * 4 + 1], q2 = q[i * 4 + 2], q3 = q[i * 4 + 3];
                d0 += q0.x * k0.x + q0.y * k0.y + q0.z * k0.z + q0.w * k0.w;
                d1 += q1.x * k1.x + q1.y * k1.y + q1.z * k1.z + q1.w * k1.w;
                d2 += q2.x * k2.x + q2.y * k2.y + q2.z * k2.z + q2.w * k2.w;
                d3 += q3.x * k3.x + q3.y * k3.y + q3.z * k3.z + q3.w * k3.w;
            }
            s[iy * 7 + ix] = (d0 + d1) + (d2 + d3) + __ldg(&rpb[bias_base + iy * 13 + ix]);
        }
    }
    __syncthreads();   // everyone done reading K

    // Restage with V halo
    {
        const float4* gv4 = (const float4*)g_v;
        float4* s4 = (float4*)KVs;
        for (int i = tid; i < 14 * 14 * 32; i += 256) {
            int ny  = i / 448;
            int rem = i - ny * 448;
            int nx  = rem >> 5;
            int c4  = rem & 31;
            s4[(ny * 14 + nx) * 33 + c4] =
                gv4[(((b * 64 + hb + ny) * 64) + wb + nx) * 32 + c4];
        }
    }

    // softmax in registers (overlaps with V staging)
    float m = s[0];
    #pragma unroll
    for (int i = 1; i < 49; i++) m = fmaxf(m, s[i]);
    float l = 0.f;
    #pragma unroll
    for (int i = 0; i < 49; i++) { s[i] = __expf(s[i] - m); l += s[i]; }
    const float inv_l = 1.0f / l;
    __syncthreads();

    // Pass 2: attn @ V
    float4 acc[8];
    #pragma unroll
    for (int i = 0; i < 8; i++) acc[i] = make_float4(0.f, 0.f, 0.f, 0.f);

    #pragma unroll
    for (int iy = 0; iy < 7; iy++) {
        #pragma unroll
        for (int ix = 0; ix < 7; ix++) {
            const float p = s[iy * 7 + ix];
            const float* vp = &KVs[((ry + iy) * 14 + (rx + ix)) * SM_STRIDE + head * 32];
            #pragma unroll
            for (int i = 0; i < 8; i++) {
                float4 v4 = *(const float4*)&vp[i * 4];
                acc[i].x += p * v4.x;
                acc[i].y += p * v4.y;
                acc[i].z += p * v4.z;
                acc[i].w += p * v4.w;
            }
        }
    }

    float4* out4 = (float4*)g_att;
    int obase = pixel * 32 + head * 8;
    #pragma unroll
    for (int i = 0; i < 8; i++) {
        out4[obase + i] = make_float4(acc[i].x * inv_l, acc[i].y * inv_l,
                                      acc[i].z * inv_l, acc[i].w * inv_l);
    }
}

// ---------------------------------------------------------------------------
extern "C" void kernel_launch(void* const* d_in, const int* in_sizes, int n_in,
                              void* d_out, int out_size)
{
    const float* x      = (const float*)d_in[0];
    const float* w_qkv  = (const float*)d_in[1];
    const float* b_qkv  = (const float*)d_in[2];
    const float* rpb    = (const float*)d_in[3];
    const float* w_proj = (const float*)d_in[4];
    const float* b_proj = (const float*)d_in[5];
    float* out = (float*)d_out;

    cudaFuncSetAttribute(natten_kernel,
                         cudaFuncAttributeMaxDynamicSharedMemorySize,
                         SM_FLOATS * (int)sizeof(float));
    cudaFuncSetAttribute((const void*)gemm_tf32<384, true>,
                         cudaFuncAttributeMaxDynamicSharedMemorySize, GEMM_SMEM);
    cudaFuncSetAttribute((const void*)gemm_tf32<128, false>,
                         cudaFuncAttributeMaxDynamicSharedMemorySize, GEMM_SMEM);

    gemm_tf32<384, true><<<dim3(256, 3), 256, GEMM_SMEM>>>(x, w_qkv, b_qkv, nullptr);
    natten_kernel<<<256, 256, SM_FLOATS * sizeof(float)>>>(rpb);
    gemm_tf32<128, false><<<dim3(256, 1), 256, GEMM_SMEM>>>(nullptr, w_proj, b_proj, out);
}

// round 8
// speedup vs baseline: 1.1993x; 1.1993x over previous
#include <cuda_runtime.h>
#include <cuda_fp16.h>
#include <math.h>
#include <stdint.h>

#define NPIX  16384   // 4*64*64
#define CDIM  128

// Scratch (device globals: no allocations allowed)
__device__ float g_q[NPIX * CDIM];
__device__ float g_k[NPIX * CDIM];
__device__ float g_v[NPIX * CDIM];
__device__ float g_att[NPIX * CDIM];

// ---------------- fp16 mma helpers ----------------
__device__ __forceinline__ uint32_t packh2(float x, float y) {
    uint32_t r;
    asm("{ .reg .f16 lo, hi;\n\t"
        "cvt.rn.f16.f32 lo, %1;\n\t"
        "cvt.rn.f16.f32 hi, %2;\n\t"
        "mov.b32 %0, {lo, hi}; }"
        : "=r"(r) : "f"(x), "f"(y));
    return r;
}
__device__ __forceinline__ void mma_f16(float* d, const uint32_t* a,
                                        uint32_t b0, uint32_t b1) {
    asm volatile(
        "mma.sync.aligned.m16n8k16.row.col.f32.f16.f16.f32 "
        "{%0,%1,%2,%3}, {%4,%5,%6,%7}, {%8,%9}, {%0,%1,%2,%3};"
        : "+f"(d[0]), "+f"(d[1]), "+f"(d[2]), "+f"(d[3])
        : "r"(a[0]), "r"(a[1]), "r"(a[2]), "r"(a[3]), "r"(b0), "r"(b1));
}

// ---------------------------------------------------------------------------
// FP16 tensor-core GEMM: BM=64, FULL K=128 resident in smem (half2-packed),
// single __syncthreads, 8 fully-unrolled k16-steps of straight-line LDS+HMMA.
// 8 warps: 2 over M (32 rows), 4 over N (32 cols). Warp tile 32x32.
// As32[row][kpair]  stride 68  (64 kpairs + pad): frag bank = 4g+t (lane id)
// Bs32[kpair][n]    stride 136 (128 n + pad):     frag bank = 8t+g (perm)
// ---------------------------------------------------------------------------
#define PA2 68
#define PB2 136
#define GEMM_SMEM ((64 * PA2 + 64 * PB2) * 4)   // 52224 B

template<int LDW, bool IS_QKV>
__global__ __launch_bounds__(256) void gemm_f16(
    const float* __restrict__ A,      // [16384, 128] (ignored for proj)
    const float* __restrict__ W,      // [128, LDW]
    const float* __restrict__ bias,   // [LDW]
    float* __restrict__ outp)         // proj output
{
    extern __shared__ uint32_t smem_g[];
    uint32_t* As32 = smem_g;                  // [64][PA2]  (m-major, k-pair minor)
    uint32_t* Bs32 = smem_g + 64 * PA2;       // [64][PB2]  (k-pair major, n minor)

    const int bm   = blockIdx.x;
    const int bn   = blockIdx.y;
    const int tid  = threadIdx.x;
    const int lane = tid & 31;
    const int wrp  = tid >> 5;
    const int g    = lane >> 2;
    const int t    = lane & 3;
    const int wm   = wrp & 1;        // 2 warps along M (32 rows each)
    const int wn   = wrp >> 1;       // 4 warps along N (32 cols each)

    const float* Aptr = IS_QKV ? A : g_att;

    // ---- Stage A: 64 rows x 128 k -> half2 pairs (8 float4 per thread)
    #pragma unroll
    for (int i = 0; i < 8; i++) {
        int f4  = tid + i * 256;             // 0..2047
        int r   = f4 >> 5;                   // row 0..63
        int c4  = f4 & 31;                   // float4 index along k
        float4 v = *(const float4*)&Aptr[(size_t)(bm * 64 + r) * 128 + c4 * 4];
        As32[r * PA2 + c4 * 2 + 0] = packh2(v.x, v.y);
        As32[r * PA2 + c4 * 2 + 1] = packh2(v.z, v.w);
    }
    // ---- Stage B: pack k-pairs: Bs32[kp][n] = (W[2kp][n], W[2kp+1][n])
    #pragma unroll
    for (int i = 0; i < 8; i++) {
        int idx = tid + i * 256;             // 0..2047
        int kp  = idx >> 5;                  // k-pair 0..63
        int ng  = idx & 31;                  // n-group of 4
        const float* w0 = &W[(size_t)(2 * kp)     * LDW + bn * 128 + ng * 4];
        const float* w1 = &W[(size_t)(2 * kp + 1) * LDW + bn * 128 + ng * 4];
        float4 a4 = *(const float4*)w0;
        float4 b4 = *(const float4*)w1;
        uint4 p;
        p.x = packh2(a4.x, b4.x);
        p.y = packh2(a4.y, b4.y);
        p.z = packh2(a4.z, b4.z);
        p.w = packh2(a4.w, b4.w);
        *(uint4*)&Bs32[kp * PB2 + ng * 4] = p;
    }
    __syncthreads();

    float acc[2][4][4];
    #pragma unroll
    for (int i = 0; i < 2; i++)
        #pragma unroll
        for (int j = 0; j < 4; j++)
            #pragma unroll
            for (int c = 0; c < 4; c++) acc[i][j][c] = 0.f;

    // ---- Main loop: 8 k16-steps, fully unrolled, no syncs, no branches
    #pragma unroll
    for (int ks = 0; ks < 8; ks++) {
        const int kp0 = ks * 8;              // k-pair base
        uint32_t a[2][4];
        #pragma unroll
        for (int mi = 0; mi < 2; mi++) {
            int rb = wm * 32 + mi * 16;
            a[mi][0] = As32[(rb + g)     * PA2 + kp0 + t];
            a[mi][1] = As32[(rb + g + 8) * PA2 + kp0 + t];
            a[mi][2] = As32[(rb + g)     * PA2 + kp0 + 4 + t];
            a[mi][3] = As32[(rb + g + 8) * PA2 + kp0 + 4 + t];
        }
        #pragma unroll
        for (int ni = 0; ni < 4; ni++) {
            int cb = wn * 32 + ni * 8;
            uint32_t b0 = Bs32[(kp0 + t)     * PB2 + cb + g];
            uint32_t b1 = Bs32[(kp0 + 4 + t) * PB2 + cb + g];
            mma_f16(acc[0][ni], a[0], b0, b1);
            mma_f16(acc[1][ni], a[1], b0, b1);
        }
    }

    // ---- Epilogue
    const float scale = (IS_QKV && bn == 0) ? 0.17677669529663688f : 1.0f;
    float* dst;
    if (IS_QKV) dst = (bn == 0) ? g_q : (bn == 1) ? g_k : g_v;
    else        dst = outp;

    #pragma unroll
    for (int ni = 0; ni < 4; ni++) {
        int c  = wn * 32 + ni * 8 + t * 2;
        float b0 = bias[(IS_QKV ? bn * 128 : 0) + c];
        float b1 = bias[(IS_QKV ? bn * 128 : 0) + c + 1];
        #pragma unroll
        for (int mi = 0; mi < 2; mi++) {
            int r0 = bm * 64 + wm * 32 + mi * 16 + g;
            float2 v0 = make_float2((acc[mi][ni][0] + b0) * scale,
                                    (acc[mi][ni][1] + b1) * scale);
            float2 v1 = make_float2((acc[mi][ni][2] + b0) * scale,
                                    (acc[mi][ni][3] + b1) * scale);
            *(float2*)&dst[(size_t)r0 * 128 + c]       = v0;
            *(float2*)&dst[(size_t)(r0 + 8) * 128 + c] = v1;
        }
    }
}

// ---------------------------------------------------------------------------
// Neighborhood attention (unchanged): 8x8 pixel tile, ONE 14x14 halo buffer
// reused (K for score pass, then restaged with V) -> 103.5KB smem, 2 CTAs/SM.
// ---------------------------------------------------------------------------
#define SM_STRIDE 132                       // floats per (ny,nx) entry
#define SM_FLOATS (14 * 14 * SM_STRIDE)     // 25872 floats = 103488 B

__global__ __launch_bounds__(256, 2) void natten_kernel(const float* __restrict__ rpb)
{
    extern __shared__ float sm[];
    float* KVs = sm;

    const int tid  = threadIdx.x;
    const int tile = blockIdx.x & 63;
    const int b    = blockIdx.x >> 6;
    const int Y    = (tile >> 3) * 8;
    const int X    = (tile & 7) * 8;

    const int hb = min(max(Y - 3, 0), 50);
    const int wb = min(max(X - 3, 0), 50);

    // Stage K halo
    {
        const float4* gk4 = (const float4*)g_k;
        float4* s4 = (float4*)KVs;
        for (int i = tid; i < 14 * 14 * 32; i += 256) {
            int ny  = i / 448;
            int rem = i - ny * 448;
            int nx  = rem >> 5;
            int c4  = rem & 31;
            s4[(ny * 14 + nx) * 33 + c4] =
                gk4[(((b * 64 + hb + ny) * 64) + wb + nx) * 32 + c4];
        }
    }

    const int px   = tid & 63;
    const int head = tid >> 6;
    const int py   = px >> 3;
    const int pxx  = px & 7;
    const int y    = Y + py;
    const int x    = X + pxx;
    const int pixel = (b * 64 + y) * 64 + x;

    const int sh = min(max(y - 3, 0), 57);
    const int sw = min(max(x - 3, 0), 57);
    const int ry = sh - hb;
    const int rx = sw - wb;
    const int bias_base = head * 169 + (sh - y + 6) * 13 + (sw - x + 6);

    float4 q[8];
    {
        const float4* gq4 = (const float4*)g_q;
        int base = pixel * 32 + head * 8;
        #pragma unroll
        for (int i = 0; i < 8; i++) q[i] = gq4[base + i];
    }
    __syncthreads();

    // Pass 1: scores
    float s[49];
    #pragma unroll
    for (int iy = 0; iy < 7; iy++) {
        #pragma unroll
        for (int ix = 0; ix < 7; ix++) {
            const float* kp = &KVs[((ry + iy) * 14 + (rx + ix)) * SM_STRIDE + head * 32];
            float d0 = 0.f, d1 = 0.f, d2 = 0.f, d3 = 0.f;
            #pragma unroll
            for (int i = 0; i < 2; i++) {
                float4 k0 = *(const float4*)&kp[i * 16 + 0];
                float4 k1 = *(const float4*)&kp[i * 16 + 4];
                float4 k2 = *(const float4*)&kp[i * 16 + 8];
                float4 k3 = *(const float4*)&kp[i * 16 + 12];
                float4 q0 = q[i * 4 + 0], q1 = q[i * 4 + 1], q2 = q[i * 4 + 2], q3 = q[i * 4 + 3];
                d0 += q0.x * k0.x + q0.y * k0.y + q0.z * k0.z + q0.w * k0.w;
                d1 += q1.x * k1.x + q1.y * k1.y + q1.z * k1.z + q1.w * k1.w;
                d2 += q2.x * k2.x + q2.y * k2.y + q2.z * k2.z + q2.w * k2.w;
                d3 += q3.x * k3.x + q3.y * k3.y + q3.z * k3.z + q3.w * k3.w;
            }
            s[iy * 7 + ix] = (d0 + d1) + (d2 + d3) + __ldg(&rpb[bias_base + iy * 13 + ix]);
        }
    }
    __syncthreads();   // everyone done reading K

    // Restage with V halo
    {
        const float4* gv4 = (const float4*)g_v;
        float4* s4 = (float4*)KVs;
        for (int i = tid; i < 14 * 14 * 32; i += 256) {
            int ny  = i / 448;
            int rem = i - ny * 448;
            int nx  = rem >> 5;
            int c4  = rem & 31;
            s4[(ny * 14 + nx) * 33 + c4] =
                gv4[(((b * 64 + hb + ny) * 64) + wb + nx) * 32 + c4];
        }
    }

    // softmax in registers (overlaps with V staging)
    float m = s[0];
    #pragma unroll
    for (int i = 1; i < 49; i++) m = fmaxf(m, s[i]);
    float l = 0.f;
    #pragma unroll
    for (int i = 0; i < 49; i++) { s[i] = __expf(s[i] - m); l += s[i]; }
    const float inv_l = 1.0f / l;
    __syncthreads();

    // Pass 2: attn @ V
    float4 acc[8];
    #pragma unroll
    for (int i = 0; i < 8; i++) acc[i] = make_float4(0.f, 0.f, 0.f, 0.f);

    #pragma unroll
    for (int iy = 0; iy < 7; iy++) {
        #pragma unroll
        for (int ix = 0; ix < 7; ix++) {
            const float p = s[iy * 7 + ix];
            const float* vp = &KVs[((ry + iy) * 14 + (rx + ix)) * SM_STRIDE + head * 32];
            #pragma unroll
            for (int i = 0; i < 8; i++) {
                float4 v4 = *(const float4*)&vp[i * 4];
                acc[i].x += p * v4.x;
                acc[i].y += p * v4.y;
                acc[i].z += p * v4.z;
                acc[i].w += p * v4.w;
            }
        }
    }

    float4* out4 = (float4*)g_att;
    int obase = pixel * 32 + head * 8;
    #pragma unroll
    for (int i = 0; i < 8; i++) {
        out4[obase + i] = make_float4(acc[i].x * inv_l, acc[i].y * inv_l,
                                      acc[i].z * inv_l, acc[i].w * inv_l);
    }
}

// ---------------------------------------------------------------------------
extern "C" void kernel_launch(void* const* d_in, const int* in_sizes, int n_in,
                              void* d_out, int out_size)
{
    const float* x      = (const float*)d_in[0];
    const float* w_qkv  = (const float*)d_in[1];
    const float* b_qkv  = (const float*)d_in[2];
    const float* rpb    = (const float*)d_in[3];
    const float* w_proj = (const float*)d_in[4];
    const float* b_proj = (const float*)d_in[5];
    float* out = (float*)d_out;

    cudaFuncSetAttribute(natten_kernel,
                         cudaFuncAttributeMaxDynamicSharedMemorySize,
                         SM_FLOATS * (int)sizeof(float));
    cudaFuncSetAttribute((const void*)gemm_f16<384, true>,
                         cudaFuncAttributeMaxDynamicSharedMemorySize, GEMM_SMEM);
    cudaFuncSetAttribute((const void*)gemm_f16<128, false>,
                         cudaFuncAttributeMaxDynamicSharedMemorySize, GEMM_SMEM);

    gemm_f16<384, true><<<dim3(256, 3), 256, GEMM_SMEM>>>(x, w_qkv, b_qkv, nullptr);
    natten_kernel<<<256, 256, SM_FLOATS * sizeof(float)>>>(rpb);
    gemm_f16<128, false><<<dim3(256, 1), 256, GEMM_SMEM>>>(nullptr, w_proj, b_proj, out);
}

// round 9
// speedup vs baseline: 1.4006x; 1.1678x over previous
#include <cuda_runtime.h>
#include <cuda_fp16.h>
#include <math.h>
#include <stdint.h>

#define NPIX  16384   // 4*64*64
#define CDIM  128

// Scratch (device globals: no allocations allowed)
__device__ uint32_t g_qh[NPIX * 64];   // half2-packed q
__device__ uint32_t g_kh[NPIX * 64];   // half2-packed k
__device__ uint32_t g_vh[NPIX * 64];   // half2-packed v
__device__ float    g_att[NPIX * CDIM];
__device__ uint32_t g_wpack[4 * 64 * 128];  // [slice][kpair][n] half2(W[2kp][n],W[2kp+1][n])

// ---------------- fp16 mma helpers ----------------
__device__ __forceinline__ uint32_t packh2(float x, float y) {
    uint32_t r;
    asm("{ .reg .f16 lo, hi;\n\t"
        "cvt.rn.f16.f32 lo, %1;\n\t"
        "cvt.rn.f16.f32 hi, %2;\n\t"
        "mov.b32 %0, {lo, hi}; }"
        : "=r"(r) : "f"(x), "f"(y));
    return r;
}
__device__ __forceinline__ __half2 as_h2(uint32_t w) {
    return *(__half2*)&w;
}
__device__ __forceinline__ void mma_f16(float* d, const uint32_t* a,
                                        uint32_t b0, uint32_t b1) {
    asm volatile(
        "mma.sync.aligned.m16n8k16.row.col.f32.f16.f16.f32 "
        "{%0,%1,%2,%3}, {%4,%5,%6,%7}, {%8,%9}, {%0,%1,%2,%3};"
        : "+f"(d[0]), "+f"(d[1]), "+f"(d[2]), "+f"(d[3])
        : "r"(a[0]), "r"(a[1]), "r"(a[2]), "r"(a[3]), "r"(b0), "r"(b1));
}

// ---------------------------------------------------------------------------
// Prep: pack weights into half2 k-pair layout. id = slice*8192 + kp*128 + n
// ---------------------------------------------------------------------------
__global__ __launch_bounds__(256) void prep_w(
    const float* __restrict__ wq,      // [128, 384]
    const float* __restrict__ wp)      // [128, 128]
{
    int id    = blockIdx.x * 256 + threadIdx.x;   // 0..32767
    int slice = id >> 13;
    int kp    = (id >> 7) & 63;
    int n     = id & 127;
    float a, b;
    if (slice < 3) {
        a = wq[(size_t)(2 * kp)     * 384 + slice * 128 + n];
        b = wq[(size_t)(2 * kp + 1) * 384 + slice * 128 + n];
    } else {
        a = wp[(size_t)(2 * kp)     * 128 + n];
        b = wp[(size_t)(2 * kp + 1) * 128 + n];
    }
    g_wpack[id] = packh2(a, b);
}

// ---------------------------------------------------------------------------
// FP16 tensor-core GEMM: BM=64, FULL K=128 resident, single sync, 8 unrolled
// k16-steps. 8 warps: 2 over M, 4 over N. Warp tile 32x32.
// As32[row][kpair]  stride 68 : frag bank = 4g+t (lane id)
// Bs32[kpair][n]    stride 136: frag bank = 8t+g (perm)
// ---------------------------------------------------------------------------
#define PA2 68
#define PB2 136
#define GEMM_SMEM ((64 * PA2 + 64 * PB2) * 4)   // 52224 B

template<bool IS_QKV>
__global__ __launch_bounds__(256) void gemm_f16(
    const float* __restrict__ A,      // qkv: x [16384,128]; proj: unused
    const float* __restrict__ bias,   // [LDW]
    float* __restrict__ outp)         // proj output
{
    extern __shared__ uint32_t smem_g[];
    uint32_t* As32 = smem_g;                  // [64][PA2]
    uint32_t* Bs32 = smem_g + 64 * PA2;       // [64][PB2]

    const int bm    = blockIdx.x;
    const int bn    = IS_QKV ? blockIdx.y : 0;
    const int slice = IS_QKV ? bn : 3;
    const int tid   = threadIdx.x;
    const int lane  = tid & 31;
    const int wrp   = tid >> 5;
    const int g     = lane >> 2;
    const int t     = lane & 3;
    const int wm    = wrp & 1;
    const int wn    = wrp >> 1;

    const float* Aptr = IS_QKV ? A : g_att;

    // ---- Stage A: 64 rows x 128 k -> half2 pairs
    #pragma unroll
    for (int i = 0; i < 8; i++) {
        int f4  = tid + i * 256;
        int r   = f4 >> 5;
        int c4  = f4 & 31;
        float4 v = *(const float4*)&Aptr[(size_t)(bm * 64 + r) * 128 + c4 * 4];
        As32[r * PA2 + c4 * 2 + 0] = packh2(v.x, v.y);
        As32[r * PA2 + c4 * 2 + 1] = packh2(v.z, v.w);
    }
    // ---- Stage B: pure uint4 copies from pre-packed weights
    {
        const uint4* wp4 = (const uint4*)g_wpack;
        uint4* Bs4 = (uint4*)Bs32;
        #pragma unroll
        for (int i = 0; i < 8; i++) {
            int idx = tid + i * 256;
            int kp  = idx >> 5;
            int ng  = idx & 31;
            Bs4[kp * 34 + ng] = wp4[slice * 2048 + kp * 32 + ng];
        }
    }
    __syncthreads();

    float acc[2][4][4];
    #pragma unroll
    for (int i = 0; i < 2; i++)
        #pragma unroll
        for (int j = 0; j < 4; j++)
            #pragma unroll
            for (int c = 0; c < 4; c++) acc[i][j][c] = 0.f;

    #pragma unroll
    for (int ks = 0; ks < 8; ks++) {
        const int kp0 = ks * 8;
        uint32_t a[2][4];
        #pragma unroll
        for (int mi = 0; mi < 2; mi++) {
            int rb = wm * 32 + mi * 16;
            a[mi][0] = As32[(rb + g)     * PA2 + kp0 + t];
            a[mi][1] = As32[(rb + g + 8) * PA2 + kp0 + t];
            a[mi][2] = As32[(rb + g)     * PA2 + kp0 + 4 + t];
            a[mi][3] = As32[(rb + g + 8) * PA2 + kp0 + 4 + t];
        }
        #pragma unroll
        for (int ni = 0; ni < 4; ni++) {
            int cb = wn * 32 + ni * 8;
            uint32_t b0 = Bs32[(kp0 + t)     * PB2 + cb + g];
            uint32_t b1 = Bs32[(kp0 + 4 + t) * PB2 + cb + g];
            mma_f16(acc[0][ni], a[0], b0, b1);
            mma_f16(acc[1][ni], a[1], b0, b1);
        }
    }

    // ---- Epilogue
    const float scale = (IS_QKV && bn == 0) ? 0.17677669529663688f : 1.0f;

    #pragma unroll
    for (int ni = 0; ni < 4; ni++) {
        int c  = wn * 32 + ni * 8 + t * 2;
        float b0 = bias[(IS_QKV ? bn * 128 : 0) + c];
        float b1 = bias[(IS_QKV ? bn * 128 : 0) + c + 1];
        #pragma unroll
        for (int mi = 0; mi < 2; mi++) {
            int r0 = bm * 64 + wm * 32 + mi * 16 + g;
            float v00 = (acc[mi][ni][0] + b0) * scale;
            float v01 = (acc[mi][ni][1] + b1) * scale;
            float v10 = (acc[mi][ni][2] + b0) * scale;
            float v11 = (acc[mi][ni][3] + b1) * scale;
            if (IS_QKV) {
                uint32_t* gd = (bn == 0) ? g_qh : (bn == 1) ? g_kh : g_vh;
                gd[(size_t)r0 * 64       + (c >> 1)] = packh2(v00, v01);
                gd[(size_t)(r0 + 8) * 64 + (c >> 1)] = packh2(v10, v11);
            } else {
                *(float2*)&outp[(size_t)r0 * 128 + c]       = make_float2(v00, v01);
                *(float2*)&outp[(size_t)(r0 + 8) * 128 + c] = make_float2(v10, v11);
            }
        }
    }
}

// ---------------------------------------------------------------------------
// Neighborhood attention v4: 8x8 pixel tile, fp16 K AND V halos resident
// simultaneously (2 x 53.3KB, stride 68 u32 -> conflict-free LDS.128).
// Scores via HFMA2, AV accumulated fp32 from converted half V.
// ---------------------------------------------------------------------------
#define NSTRIDE4 17                          // uint4 per neighbor row (68 u32)
#define KV_U32   (196 * 68)                  // 13328 u32 = 53312 B per tensor
#define NAT_SMEM (2 * KV_U32 * 4)            // 106624 B

__global__ __launch_bounds__(256, 2) void natten_kernel(const float* __restrict__ rpb)
{
    extern __shared__ uint32_t smn[];
    uint4* Ks4 = (uint4*)smn;
    uint4* Vs4 = (uint4*)(smn + KV_U32);

    const int tid  = threadIdx.x;
    const int tile = blockIdx.x & 63;
    const int b    = blockIdx.x >> 6;
    const int Y    = (tile >> 3) * 8;
    const int X    = (tile & 7) * 8;

    const int hb = min(max(Y - 3, 0), 50);
    const int wb = min(max(X - 3, 0), 50);

    // Stage K and V halos (half2-packed): 196 neighbors x 16 uint4 each
    {
        const uint4* gk4 = (const uint4*)g_kh;
        const uint4* gv4 = (const uint4*)g_vh;
        for (int i = tid; i < 196 * 16; i += 256) {
            int nb = i >> 4;
            int j  = i & 15;
            int ny = nb / 14;
            int nx = nb - ny * 14;
            int gp = (b * 64 + hb + ny) * 64 + wb + nx;
            Ks4[nb * NSTRIDE4 + j] = gk4[gp * 16 + j];
            Vs4[nb * NSTRIDE4 + j] = gv4[gp * 16 + j];
        }
    }

    const int px    = tid & 63;
    const int head  = tid >> 6;
    const int py    = px >> 3;
    const int pxx   = px & 7;
    const int y     = Y + py;
    const int x     = X + pxx;
    const int pixel = (b * 64 + y) * 64 + x;

    const int sh = min(max(y - 3, 0), 57);
    const int sw = min(max(x - 3, 0), 57);
    const int ry = sh - hb;
    const int rx = sw - wb;
    const int bias_base = head * 169 + (sh - y + 6) * 13 + (sw - x + 6);

    // q in registers: 16 half2 (overlaps with staging)
    uint32_t qw[16];
    {
        const uint4* gq4 = (const uint4*)g_qh;
        #pragma unroll
        for (int j = 0; j < 4; j++) {
            uint4 v = gq4[pixel * 16 + head * 4 + j];
            qw[j * 4 + 0] = v.x; qw[j * 4 + 1] = v.y;
            qw[j * 4 + 2] = v.z; qw[j * 4 + 3] = v.w;
        }
    }
    __syncthreads();

    // Pass 1: scores via HFMA2
    float s[49];
    #pragma unroll
    for (int iy = 0; iy < 7; iy++) {
        #pragma unroll
        for (int ix = 0; ix < 7; ix++) {
            int nb = (ry + iy) * 14 + (rx + ix);
            const uint4* kp4 = &Ks4[nb * NSTRIDE4 + head * 4];
            __half2 a0 = __float2half2_rn(0.f), a1 = a0, a2 = a0, a3 = a0;
            #pragma unroll
            for (int j = 0; j < 4; j++) {
                uint4 kv = kp4[j];
                a0 = __hfma2(as_h2(qw[j * 4 + 0]), as_h2(kv.x), a0);
                a1 = __hfma2(as_h2(qw[j * 4 + 1]), as_h2(kv.y), a1);
                a2 = __hfma2(as_h2(qw[j * 4 + 2]), as_h2(kv.z), a2);
                a3 = __hfma2(as_h2(qw[j * 4 + 3]), as_h2(kv.w), a3);
            }
            a0 = __hadd2(a0, a1);
            a2 = __hadd2(a2, a3);
            float2 f = __half22float2(__hadd2(a0, a2));
            s[iy * 7 + ix] = f.x + f.y + __ldg(&rpb[bias_base + iy * 13 + ix]);
        }
    }

    // softmax in registers
    float m = s[0];
    #pragma unroll
    for (int i = 1; i < 49; i++) m = fmaxf(m, s[i]);
    float l = 0.f;
    #pragma unroll
    for (int i = 0; i < 49; i++) { s[i] = __expf(s[i] - m); l += s[i]; }
    const float inv_l = 1.0f / l;

    // Pass 2: attn @ V (fp32 accumulate from half V)
    float2 acc[16];
    #pragma unroll
    for (int i = 0; i < 16; i++) acc[i] = make_float2(0.f, 0.f);

    #pragma unroll
    for (int iy = 0; iy < 7; iy++) {
        #pragma unroll
        for (int ix = 0; ix < 7; ix++) {
            const float p = s[iy * 7 + ix];
            int nb = (ry + iy) * 14 + (rx + ix);
            const uint4* vp4 = &Vs4[nb * NSTRIDE4 + head * 4];
            #pragma unroll
            for (int j = 0; j < 4; j++) {
                uint4 vv = vp4[j];
                float2 f0 = __half22float2(as_h2(vv.x));
                float2 f1 = __half22float2(as_h2(vv.y));
                float2 f2 = __half22float2(as_h2(vv.z));
                float2 f3 = __half22float2(as_h2(vv.w));
                acc[j*4+0].x += p * f0.x; acc[j*4+0].y += p * f0.y;
                acc[j*4+1].x += p * f1.x; acc[j*4+1].y += p * f1.y;
                acc[j*4+2].x += p * f2.x; acc[j*4+2].y += p * f2.y;
                acc[j*4+3].x += p * f3.x; acc[j*4+3].y += p * f3.y;
            }
        }
    }

    float4* out4 = (float4*)g_att;
    int obase = pixel * 32 + head * 8;
    #pragma unroll
    for (int i = 0; i < 8; i++) {
        out4[obase + i] = make_float4(acc[2*i].x * inv_l, acc[2*i].y * inv_l,
                                      acc[2*i+1].x * inv_l, acc[2*i+1].y * inv_l);
    }
}

// ---------------------------------------------------------------------------
extern "C" void kernel_launch(void* const* d_in, const int* in_sizes, int n_in,
                              void* d_out, int out_size)
{
    const float* x      = (const float*)d_in[0];
    const float* w_qkv  = (const float*)d_in[1];
    const float* b_qkv  = (const float*)d_in[2];
    const float* rpb    = (const float*)d_in[3];
    const float* w_proj = (const float*)d_in[4];
    const float* b_proj = (const float*)d_in[5];
    float* out = (float*)d_out;

    cudaFuncSetAttribute(natten_kernel,
                         cudaFuncAttributeMaxDynamicSharedMemorySize, NAT_SMEM);
    cudaFuncSetAttribute((const void*)gemm_f16<true>,
                         cudaFuncAttributeMaxDynamicSharedMemorySize, GEMM_SMEM);
    cudaFuncSetAttribute((const void*)gemm_f16<false>,
                         cudaFuncAttributeMaxDynamicSharedMemorySize, GEMM_SMEM);

    prep_w<<<128, 256>>>(w_qkv, w_proj);
    gemm_f16<true><<<dim3(256, 3), 256, GEMM_SMEM>>>(x, b_qkv, nullptr);
    natten_kernel<<<256, 256, NAT_SMEM>>>(rpb);
    gemm_f16<false><<<dim3(256, 1), 256, GEMM_SMEM>>>(nullptr, b_proj, out);
}

// round 10
// speedup vs baseline: 1.6026x; 1.1442x over previous
#include <cuda_runtime.h>
#include <cuda_fp16.h>
#include <math.h>
#include <stdint.h>

#define NPIX  16384   // 4*64*64
#define CDIM  128

// Scratch (device globals: no allocations allowed)
__device__ uint32_t g_qh[NPIX * 64];   // half2-packed q
__device__ uint32_t g_kh[NPIX * 64];   // half2-packed k
__device__ uint32_t g_vh[NPIX * 64];   // half2-packed v
__device__ uint32_t g_wpack[4 * 64 * 128];  // [slice][kpair][n] half2(W[2kp][n],W[2kp+1][n])

// ---------------- fp16 mma helpers ----------------
__device__ __forceinline__ uint32_t packh2(float x, float y) {
    uint32_t r;
    asm("{ .reg .f16 lo, hi;\n\t"
        "cvt.rn.f16.f32 lo, %1;\n\t"
        "cvt.rn.f16.f32 hi, %2;\n\t"
        "mov.b32 %0, {lo, hi}; }"
        : "=r"(r) : "f"(x), "f"(y));
    return r;
}
__device__ __forceinline__ __half2 as_h2(uint32_t w) {
    return *(__half2*)&w;
}
__device__ __forceinline__ void mma_f16(float* d, const uint32_t* a,
                                        uint32_t b0, uint32_t b1) {
    asm volatile(
        "mma.sync.aligned.m16n8k16.row.col.f32.f16.f16.f32 "
        "{%0,%1,%2,%3}, {%4,%5,%6,%7}, {%8,%9}, {%0,%1,%2,%3};"
        : "+f"(d[0]), "+f"(d[1]), "+f"(d[2]), "+f"(d[3])
        : "r"(a[0]), "r"(a[1]), "r"(a[2]), "r"(a[3]), "r"(b0), "r"(b1));
}

// ---------------------------------------------------------------------------
// Prep: pack weights into half2 k-pair layout. id = slice*8192 + kp*128 + n
// slice 0..2 = qkv slices, 3 = proj.
// ---------------------------------------------------------------------------
__global__ __launch_bounds__(256) void prep_w(
    const float* __restrict__ wq,      // [128, 384]
    const float* __restrict__ wp)      // [128, 128]
{
    int id    = blockIdx.x * 256 + threadIdx.x;   // 0..32767
    int slice = id >> 13;
    int kp    = (id >> 7) & 63;
    int n     = id & 127;
    float a, b;
    if (slice < 3) {
        a = wq[(size_t)(2 * kp)     * 384 + slice * 128 + n];
        b = wq[(size_t)(2 * kp + 1) * 384 + slice * 128 + n];
    } else {
        a = wp[(size_t)(2 * kp)     * 128 + n];
        b = wp[(size_t)(2 * kp + 1) * 128 + n];
    }
    g_wpack[id] = packh2(a, b);
}

// ---------------------------------------------------------------------------
// FP16 tensor-core QKV GEMM: BM=64, FULL K=128 resident, single sync,
// 8 unrolled k16-steps. 8 warps: 2 over M, 4 over N. Warp tile 32x32.
// As32[row][kpair]  stride 68 : frag bank = 4g+t (lane id)
// Bs32[kpair][n]    stride 136: frag bank = 8t+g (perm)
// ---------------------------------------------------------------------------
#define PA2 68
#define PB2 136
#define GEMM_SMEM ((64 * PA2 + 64 * PB2) * 4)   // 52224 B

__global__ __launch_bounds__(256) void gemm_qkv(
    const float* __restrict__ A,      // x [16384,128]
    const float* __restrict__ bias)   // [384]
{
    extern __shared__ uint32_t smem_g[];
    uint32_t* As32 = smem_g;                  // [64][PA2]
    uint32_t* Bs32 = smem_g + 64 * PA2;       // [64][PB2]

    const int bm    = blockIdx.x;
    const int bn    = blockIdx.y;
    const int tid   = threadIdx.x;
    const int lane  = tid & 31;
    const int wrp   = tid >> 5;
    const int g     = lane >> 2;
    const int t     = lane & 3;
    const int wm    = wrp & 1;
    const int wn    = wrp >> 1;

    // ---- Stage A: 64 rows x 128 k -> half2 pairs
    #pragma unroll
    for (int i = 0; i < 8; i++) {
        int f4  = tid + i * 256;
        int r   = f4 >> 5;
        int c4  = f4 & 31;
        float4 v = *(const float4*)&A[(size_t)(bm * 64 + r) * 128 + c4 * 4];
        As32[r * PA2 + c4 * 2 + 0] = packh2(v.x, v.y);
        As32[r * PA2 + c4 * 2 + 1] = packh2(v.z, v.w);
    }
    // ---- Stage B: pure uint4 copies from pre-packed weights
    {
        const uint4* wp4 = (const uint4*)g_wpack;
        uint4* Bs4 = (uint4*)Bs32;
        #pragma unroll
        for (int i = 0; i < 8; i++) {
            int idx = tid + i * 256;
            int kp  = idx >> 5;
            int ng  = idx & 31;
            Bs4[kp * 34 + ng] = wp4[bn * 2048 + kp * 32 + ng];
        }
    }
    __syncthreads();

    float acc[2][4][4];
    #pragma unroll
    for (int i = 0; i < 2; i++)
        #pragma unroll
        for (int j = 0; j < 4; j++)
            #pragma unroll
            for (int c = 0; c < 4; c++) acc[i][j][c] = 0.f;

    #pragma unroll
    for (int ks = 0; ks < 8; ks++) {
        const int kp0 = ks * 8;
        uint32_t a[2][4];
        #pragma unroll
        for (int mi = 0; mi < 2; mi++) {
            int rb = wm * 32 + mi * 16;
            a[mi][0] = As32[(rb + g)     * PA2 + kp0 + t];
            a[mi][1] = As32[(rb + g + 8) * PA2 + kp0 + t];
            a[mi][2] = As32[(rb + g)     * PA2 + kp0 + 4 + t];
            a[mi][3] = As32[(rb + g + 8) * PA2 + kp0 + 4 + t];
        }
        #pragma unroll
        for (int ni = 0; ni < 4; ni++) {
            int cb = wn * 32 + ni * 8;
            uint32_t b0 = Bs32[(kp0 + t)     * PB2 + cb + g];
            uint32_t b1 = Bs32[(kp0 + 4 + t) * PB2 + cb + g];
            mma_f16(acc[0][ni], a[0], b0, b1);
            mma_f16(acc[1][ni], a[1], b0, b1);
        }
    }

    // ---- Epilogue: pack to half2 globals
    const float scale = (bn == 0) ? 0.17677669529663688f : 1.0f;
    uint32_t* gd = (bn == 0) ? g_qh : (bn == 1) ? g_kh : g_vh;

    #pragma unroll
    for (int ni = 0; ni < 4; ni++) {
        int c  = wn * 32 + ni * 8 + t * 2;
        float b0 = bias[bn * 128 + c];
        float b1 = bias[bn * 128 + c + 1];
        #pragma unroll
        for (int mi = 0; mi < 2; mi++) {
            int r0 = bm * 64 + wm * 32 + mi * 16 + g;
            gd[(size_t)r0 * 64       + (c >> 1)] =
                packh2((acc[mi][ni][0] + b0) * scale, (acc[mi][ni][1] + b1) * scale);
            gd[(size_t)(r0 + 8) * 64 + (c >> 1)] =
                packh2((acc[mi][ni][2] + b0) * scale, (acc[mi][ni][3] + b1) * scale);
        }
    }
}

// ---------------------------------------------------------------------------
// Fused neighborhood attention + output projection.
// Phase 1-2: 8x8 pixel tile, fp16 K/V halos in smem, per-thread softmax.
// Phase 3: attention output -> fp16 smem tile (reusing K region), W_proj
//          staged into V region, 8-warp m16n8k16 GEMM writes d_out directly.
// ---------------------------------------------------------------------------
#define NSTRIDE4 17                          // uint4 per neighbor row (68 u32)
#define KV_U32   (196 * 68)                  // 13328 u32 = 53312 B per tensor
#define NAT_SMEM (2 * KV_U32 * 4)            // 106624 B

__global__ __launch_bounds__(256, 2) void natten_proj_kernel(
    const float* __restrict__ rpb,
    const float* __restrict__ b_proj,
    float* __restrict__ out)
{
    extern __shared__ uint32_t smn[];
    uint4* Ks4 = (uint4*)smn;
    uint4* Vs4 = (uint4*)(smn + KV_U32);
    uint32_t* AT32 = smn;                    // reuses K region after pass 1
    uint32_t* BP32 = smn + KV_U32;           // reuses V region after pass 2

    const int tid  = threadIdx.x;
    const int tile = blockIdx.x & 63;
    const int b    = blockIdx.x >> 6;
    const int Y    = (tile >> 3) * 8;
    const int X    = (tile & 7) * 8;

    const int hb = min(max(Y - 3, 0), 50);
    const int wb = min(max(X - 3, 0), 50);

    // Stage K and V halos (half2-packed): 196 neighbors x 16 uint4 each
    {
        const uint4* gk4 = (const uint4*)g_kh;
        const uint4* gv4 = (const uint4*)g_vh;
        for (int i = tid; i < 196 * 16; i += 256) {
            int nb = i >> 4;
            int j  = i & 15;
            int ny = nb / 14;
            int nx = nb - ny * 14;
            int gp = (b * 64 + hb + ny) * 64 + wb + nx;
            Ks4[nb * NSTRIDE4 + j] = gk4[gp * 16 + j];
            Vs4[nb * NSTRIDE4 + j] = gv4[gp * 16 + j];
        }
    }

    const int px    = tid & 63;
    const int head  = tid >> 6;
    const int py    = px >> 3;
    const int pxx   = px & 7;
    const int y     = Y + py;
    const int x     = X + pxx;
    const int pixel = (b * 64 + y) * 64 + x;

    const int sh = min(max(y - 3, 0), 57);
    const int sw = min(max(x - 3, 0), 57);
    const int ry = sh - hb;
    const int rx = sw - wb;
    const int bias_base = head * 169 + (sh - y + 6) * 13 + (sw - x + 6);

    // q in registers: 16 half2 (overlaps with staging)
    uint32_t qw[16];
    {
        const uint4* gq4 = (const uint4*)g_qh;
        #pragma unroll
        for (int j = 0; j < 4; j++) {
            uint4 v = gq4[pixel * 16 + head * 4 + j];
            qw[j * 4 + 0] = v.x; qw[j * 4 + 1] = v.y;
            qw[j * 4 + 2] = v.z; qw[j * 4 + 3] = v.w;
        }
    }
    __syncthreads();

    // Pass 1: scores via HFMA2
    float s[49];
    #pragma unroll
    for (int iy = 0; iy < 7; iy++) {
        #pragma unroll
        for (int ix = 0; ix < 7; ix++) {
            int nb = (ry + iy) * 14 + (rx + ix);
            const uint4* kp4 = &Ks4[nb * NSTRIDE4 + head * 4];
            __half2 a0 = __float2half2_rn(0.f), a1 = a0, a2 = a0, a3 = a0;
            #pragma unroll
            for (int j = 0; j < 4; j++) {
                uint4 kv = kp4[j];
                a0 = __hfma2(as_h2(qw[j * 4 + 0]), as_h2(kv.x), a0);
                a1 = __hfma2(as_h2(qw[j * 4 + 1]), as_h2(kv.y), a1);
                a2 = __hfma2(as_h2(qw[j * 4 + 2]), as_h2(kv.z), a2);
                a3 = __hfma2(as_h2(qw[j * 4 + 3]), as_h2(kv.w), a3);
            }
            a0 = __hadd2(a0, a1);
            a2 = __hadd2(a2, a3);
            float2 f = __half22float2(__hadd2(a0, a2));
            s[iy * 7 + ix] = f.x + f.y + __ldg(&rpb[bias_base + iy * 13 + ix]);
        }
    }
    __syncthreads();   // all K reads done (K region may be overwritten below)

    // softmax in registers
    float m = s[0];
    #pragma unroll
    for (int i = 1; i < 49; i++) m = fmaxf(m, s[i]);
    float l = 0.f;
    #pragma unroll
    for (int i = 0; i < 49; i++) { s[i] = __expf(s[i] - m); l += s[i]; }
    const float inv_l = 1.0f / l;

    // Pass 2: attn @ V (fp32 accumulate from half V)
    float2 acc[16];
    #pragma unroll
    for (int i = 0; i < 16; i++) acc[i] = make_float2(0.f, 0.f);

    #pragma unroll
    for (int iy = 0; iy < 7; iy++) {
        #pragma unroll
        for (int ix = 0; ix < 7; ix++) {
            const float p = s[iy * 7 + ix];
            int nb = (ry + iy) * 14 + (rx + ix);
            const uint4* vp4 = &Vs4[nb * NSTRIDE4 + head * 4];
            #pragma unroll
            for (int j = 0; j < 4; j++) {
                uint4 vv = vp4[j];
                float2 f0 = __half22float2(as_h2(vv.x));
                float2 f1 = __half22float2(as_h2(vv.y));
                float2 f2 = __half22float2(as_h2(vv.z));
                float2 f3 = __half22float2(as_h2(vv.w));
                acc[j*4+0].x += p * f0.x; acc[j*4+0].y += p * f0.y;
                acc[j*4+1].x += p * f1.x; acc[j*4+1].y += p * f1.y;
                acc[j*4+2].x += p * f2.x; acc[j*4+2].y += p * f2.y;
                acc[j*4+3].x += p * f3.x; acc[j*4+3].y += p * f3.y;
            }
        }
    }

    // Write attention output into K region as fp16 A-tile: AT32[row][kpair],
    // row = px (0..63), kpair = head*16 + i, stride 68.
    #pragma unroll
    for (int i = 0; i < 16; i++) {
        AT32[px * PA2 + head * 16 + i] = packh2(acc[i].x * inv_l, acc[i].y * inv_l);
    }
    __syncthreads();   // attout complete AND all V reads done

    // Stage W_proj (slice 3) into V region: BP32[kpair][n], stride 136
    {
        const uint4* wp4 = (const uint4*)g_wpack;
        uint4* Bp4 = (uint4*)BP32;
        #pragma unroll
        for (int i = 0; i < 8; i++) {
            int idx = tid + i * 256;
            int kp  = idx >> 5;
            int ng  = idx & 31;
            Bp4[kp * 34 + ng] = wp4[3 * 2048 + kp * 32 + ng];
        }
    }
    __syncthreads();

    // Proj GEMM: 64x128 = AT(64x128) @ Wp(128x128). 8 warps, warp tile 32x32.
    {
        const int lane = tid & 31;
        const int wrp  = tid >> 5;
        const int g    = lane >> 2;
        const int t    = lane & 3;
        const int wm   = wrp & 1;
        const int wn   = wrp >> 1;

        float pacc[2][4][4];
        #pragma unroll
        for (int i = 0; i < 2; i++)
            #pragma unroll
            for (int j = 0; j < 4; j++)
                #pragma unroll
                for (int c = 0; c < 4; c++) pacc[i][j][c] = 0.f;

        #pragma unroll
        for (int ks = 0; ks < 8; ks++) {
            const int kp0 = ks * 8;
            uint32_t a[2][4];
            #pragma unroll
            for (int mi = 0; mi < 2; mi++) {
                int rb = wm * 32 + mi * 16;
                a[mi][0] = AT32[(rb + g)     * PA2 + kp0 + t];
                a[mi][1] = AT32[(rb + g + 8) * PA2 + kp0 + t];
                a[mi][2] = AT32[(rb + g)     * PA2 + kp0 + 4 + t];
                a[mi][3] = AT32[(rb + g + 8) * PA2 + kp0 + 4 + t];
            }
            #pragma unroll
            for (int ni = 0; ni < 4; ni++) {
                int cb = wn * 32 + ni * 8;
                uint32_t b0 = BP32[(kp0 + t)     * PB2 + cb + g];
                uint32_t b1 = BP32[(kp0 + 4 + t) * PB2 + cb + g];
                mma_f16(pacc[0][ni], a[0], b0, b1);
                mma_f16(pacc[1][ni], a[1], b0, b1);
            }
        }

        // Epilogue: map local row -> pixel, add bias, store fp32
        #pragma unroll
        for (int ni = 0; ni < 4; ni++) {
            int c  = wn * 32 + ni * 8 + t * 2;
            float b0 = __ldg(&b_proj[c]);
            float b1 = __ldg(&b_proj[c + 1]);
            #pragma unroll
            for (int mi = 0; mi < 2; mi++) {
                int r = wm * 32 + mi * 16 + g;
                int p0 = (b * 64 + Y + (r >> 3)) * 64 + X + (r & 7);
                int r1 = r + 8;
                int p1 = (b * 64 + Y + (r1 >> 3)) * 64 + X + (r1 & 7);
                *(float2*)&out[(size_t)p0 * 128 + c] =
                    make_float2(pacc[mi][ni][0] + b0, pacc[mi][ni][1] + b1);
                *(float2*)&out[(size_t)p1 * 128 + c] =
                    make_float2(pacc[mi][ni][2] + b0, pacc[mi][ni][3] + b1);
            }
        }
    }
}

// ---------------------------------------------------------------------------
extern "C" void kernel_launch(void* const* d_in, const int* in_sizes, int n_in,
                              void* d_out, int out_size)
{
    const float* x      = (const float*)d_in[0];
    const float* w_qkv  = (const float*)d_in[1];
    const float* b_qkv  = (const float*)d_in[2];
    const float* rpb    = (const float*)d_in[3];
    const float* w_proj = (const float*)d_in[4];
    const float* b_proj = (const float*)d_in[5];
    float* out = (float*)d_out;

    cudaFuncSetAttribute(natten_proj_kernel,
                         cudaFuncAttributeMaxDynamicSharedMemorySize, NAT_SMEM);
    cudaFuncSetAttribute(gemm_qkv,
                         cudaFuncAttributeMaxDynamicSharedMemorySize, GEMM_SMEM);

    prep_w<<<128, 256>>>(w_qkv, w_proj);
    gemm_qkv<<<dim3(256, 3), 256, GEMM_SMEM>>>(x, b_qkv);
    natten_proj_kernel<<<256, 256, NAT_SMEM>>>(rpb, b_proj, out);
}